// round 9
// baseline (speedup 1.0000x reference)
#include <cuda_runtime.h>
#include <cuda_bf16.h>

#define BB 2
#define H 256
#define W 832
#define NPIX (H*W)

#define TSZ 32               // output tile 32x32
#define HALO 10
#define TY_N (H/TSZ)         // 8
#define TX_N (W/TSZ)         // 26
#define SH 56                // staged src patch: tile + halo(10) + keep-window(2) each side
#define SPITCH 57
#define KCAP 352             // >= 18*18 = 324 kept points in 52x52 halo (Chebyshev spacing >= 3)

// on-demand orientation from GLOBAL map (handles circular wrap at image borders):
// circular 3x3 box blur + edge-clamped np.gradient -> (cos, sin) of atan2
__device__ __forceinline__ void orient(const float* __restrict__ m, int i, int j,
                                       float& cs, float& ss) {
    float patch[5][5];
#pragma unroll
    for (int r = 0; r < 5; r++) {
        int ii = i + r - 2; ii += (ii < 0) ? H : 0; ii -= (ii >= H) ? H : 0;
#pragma unroll
        for (int c = 0; c < 5; c++) {
            int jj = j + c - 2; jj += (jj < 0) ? W : 0; jj -= (jj >= W) ? W : 0;
            patch[r][c] = m[ii*W + jj];
        }
    }
#define BLUR_AT(di, dj) (patch[1+di][1+dj] + patch[1+di][2+dj] + patch[1+di][3+dj] \
                       + patch[2+di][1+dj] + patch[2+di][2+dj] + patch[2+di][3+dj] \
                       + patch[3+di][1+dj] + patch[3+di][2+dj] + patch[3+di][3+dj])
    float byp = BLUR_AT(1, 0), bym = BLUR_AT(-1, 0), bc = BLUR_AT(0, 0);
    float bxp = BLUR_AT(0, 1), bxm = BLUR_AT(0, -1);
#undef BLUR_AT
    float gyv = (i == 0) ? (byp - bc) : (i == H-1) ? (bc - bym) : 0.5f * (byp - bym);
    float gxv = (j == 0) ? (bxp - bc) : (j == W-1) ? (bc - bxm) : 0.5f * (bxp - bxm);
    float r = sqrtf(gxv*gxv + gyv*gyv);
    if (r > 0.f) { cs = gxv / r; ss = gyv / r; }
    else         { cs = 1.f;     ss = 0.f;     }   // atan2(0,0)=0
}

// ---------------- single stateless kernel: stage -> sparsify -> search -> diffuse ----------------
__global__ void __launch_bounds__(256) k_all(const float* __restrict__ src,
                                             const float* __restrict__ dst,
                                             const int* __restrict__ xx,
                                             const int* __restrict__ yy, int K,
                                             float* __restrict__ out) {
    __shared__ float  s_S[SH*SPITCH];     // staged src patch, 0-filled outside image
    __shared__ float  s_wk[441];
    __shared__ int    s_kp[KCAP];         // kept points, packed (gi<<16)|gj
    __shared__ int    s_key[KCAP];        // active points, packed local (ry<<6)|rx
    __shared__ float2 s_dxy[KCAP];
    __shared__ int    s_cnt, s_m;

    int b = blockIdx.z;
    int ty0 = blockIdx.y * TSZ, tx0 = blockIdx.x * TSZ;
    int tid = threadIdx.x;
    int warp = tid >> 5, lane = tid & 31;
    const float* S = src + b*NPIX;
    const float* D = dst + b*NPIX;

    if (tid == 0) { s_cnt = 0; s_m = 0; }

    // weight LUT
    for (int h = tid; h < 441; h += 256) {
        int dy = h / 21 - 10, dx = h % 21 - 10;
        s_wk[h] = expf(-sqrtf((float)(dx*dx + dy*dy)) * 0.2f);
    }

    // stage src patch [ty0-12, ty0+43] x [tx0-12, tx0+43], 0-fill outside image
    for (int h = tid; h < SH*SH; h += 256) {
        int r = h / SH, c = h - r*SH;
        int gi = ty0 - 12 + r, gj = tx0 - 12 + c;
        float v = (gi >= 0 && gi < H && gj >= 0 && gj < W) ? S[gi*W + gj] : 0.f;
        s_S[r*SPITCH + c] = v;
    }
    __syncthreads();

    // sparsify: kept = edge with min linear index in clamped 5x5 window, over the 52x52 halo
    for (int h = tid; h < 52*52; h += 256) {
        int ry = h / 52, rx = h - ry*52;
        if (s_S[(ry+2)*SPITCH + (rx+2)] > 0.5f) {
            int gi = ty0 - 10 + ry, gj = tx0 - 10 + rx;
            int p = gi*W + gj;
            bool kept = true;
#pragma unroll
            for (int a = -2; a <= 2; a++)
#pragma unroll
                for (int c = -2; c <= 2; c++) {
                    float v = s_S[(ry+2+a)*SPITCH + (rx+2+c)];   // 0 if outside image
                    if (v > 0.5f) {
                        int q = (gi+a)*W + (gj+c);
                        if (q < p) kept = false;
                    }
                }
            if (kept) {
                int idx = atomicAdd(&s_cnt, 1);
                if (idx < KCAP) s_kp[idx] = (gi << 16) | gj;
            }
        }
    }
    __syncthreads();
    int n = min(s_cnt, KCAP);

    // search: warp per kept point, K offsets over lanes (identical math to R6)
    for (int pt = warp; pt < n; pt += 8) {
        int pp = s_kp[pt];
        int pi = pp >> 16, pj = pp & 0xffff;
        float cs, ssv;
        orient(S, pi, pj, cs, ssv);   // warp-uniform broadcast loads
        float best = 1e9f; int bk = 0x7fffffff;
        for (int k = lane; k < K; k += 32) {
            int ox = xx[k], oy = yy[k];
            int ii = pi + oy, jj = pj + ox;
            if (ii >= 0 && ii < H && jj >= 0 && jj < W) {
                int q = ii*W + jj;
                if (D[q] > 0.5f) {
                    float cd, sd;
                    orient(D, ii, jj, cd, sd);   // rare (~2 hits/point)
                    float ang = 1.0f - (cs*cd + ssv*sd);
                    float sc = 20.0f * sqrtf((float)(ox*ox + oy*oy)) + 10.5f * ang;
                    if (sc < best) { best = sc; bk = k; }
                }
            }
        }
        // warp lexicographic (score, k) min -> first-index-of-min (argmin semantics)
#pragma unroll
        for (int o = 16; o; o >>= 1) {
            float s2 = __shfl_xor_sync(0xffffffffu, best, o);
            int   k2 = __shfl_xor_sync(0xffffffffu, bk, o);
            if (s2 < best || (s2 == best && k2 < bk)) { best = s2; bk = k2; }
        }
        if (lane == 0 && best < 5e8f) {
            int idx = atomicAdd(&s_m, 1);
            s_key[idx] = ((pi - ty0 + 10) << 6) | (pj - tx0 + 10);
            s_dxy[idx] = make_float2((float)xx[bk], (float)yy[bk]);
        }
    }
    __syncthreads();
    int m = s_m;

    // diffuse: 4 rows per thread, warp-uniform row-band skip (R6 inner loop, local coords)
    int ox = tx0 + lane;
    int ybase = ty0 + 4*warp;

    float nx0=0.f,ny0=0.f,dn0=0.f, nx1=0.f,ny1=0.f,dn1=0.f;
    float nx2=0.f,ny2=0.f,dn2=0.f, nx3=0.f,ny3=0.f,dn3=0.f;

    for (int pI = 0; pI < m; pI++) {
        int pos = s_key[pI];
        int dyb = (pos >> 6) - 4*warp;             // warp-uniform; == weight ddy for row 0
        if ((unsigned)dyb > 23u) continue;         // uniform skip
        int ddx = (pos & 63) - lane;
        if ((unsigned)ddx <= 20u) {
            float2 d = s_dxy[pI];
            int base = dyb * 21 + ddx;
            if ((unsigned) dyb      <= 20u) { float wv = s_wk[base];      nx0 += wv*d.x; ny0 += wv*d.y; dn0 += wv; }
            if ((unsigned)(dyb - 1) <= 20u) { float wv = s_wk[base - 21]; nx1 += wv*d.x; ny1 += wv*d.y; dn1 += wv; }
            if ((unsigned)(dyb - 2) <= 20u) { float wv = s_wk[base - 42]; nx2 += wv*d.x; ny2 += wv*d.y; dn2 += wv; }
            if ((unsigned)(dyb - 3) <= 20u) { float wv = s_wk[base - 63]; nx3 += wv*d.x; ny3 += wv*d.y; dn3 += wv; }
        }
    }

    float* outx = out + (b*2 + 0)*NPIX;
    float* outy = out + (b*2 + 1)*NPIX;
    int q = ybase * W + ox;
    float fx = (float)ox;
    float i0 = 1.0f/(dn0+1e-6f); outx[q      ] = fx + 0.6f*nx0*i0; outy[q      ] = (float)(ybase  ) + 0.6f*ny0*i0;
    float i1 = 1.0f/(dn1+1e-6f); outx[q +   W] = fx + 0.6f*nx1*i1; outy[q +   W] = (float)(ybase+1) + 0.6f*ny1*i1;
    float i2 = 1.0f/(dn2+1e-6f); outx[q + 2*W] = fx + 0.6f*nx2*i2; outy[q + 2*W] = (float)(ybase+2) + 0.6f*ny2*i2;
    float i3 = 1.0f/(dn3+1e-6f); outx[q + 3*W] = fx + 0.6f*nx3*i3; outy[q + 3*W] = (float)(ybase+3) + 0.6f*ny3*i3;
}

extern "C" void kernel_launch(void* const* d_in, const int* in_sizes, int n_in,
                              void* d_out, int out_size) {
    const float* src = (const float*)d_in[0];
    const float* dst = (const float*)d_in[1];
    const int*   xx  = (const int*)d_in[2];
    const int*   yy  = (const int*)d_in[3];
    int K = in_sizes[2];
    float* out = (float*)d_out;

    dim3 g(TX_N, TY_N, BB);
    k_all<<<g, 256>>>(src, dst, xx, yy, K, out);
}

// round 10
// speedup vs baseline: 1.4327x; 1.4327x over previous
#include <cuda_runtime.h>
#include <cuda_bf16.h>

#define BB 2
#define H 256
#define W 832
#define NPIX (H*W)

#define TS 32
#define HALO 10
#define TY_N (H/TS)          // 8
#define TX_N (W/TS)          // 26
#define NTILE (TY_N*TX_N)    // 208 per batch
#define TCAP 352             // >= 18*18 = 324 (kept points pairwise Chebyshev >= 3 in 52x52 halo)

// per-tile binned active-point lists (zero-initialized at module load; k_diffuse re-zeroes counts)
__device__ int    g_tcnt[BB*NTILE];
__device__ int    g_tpos[BB*NTILE*TCAP];     // (i<<16)|j
__device__ float2 g_tdxy[BB*NTILE*TCAP];
__device__ float  g_wk[441];                 // weight LUT, written by k_seed block (0,0,0) each launch

// on-demand orientation: circular 3x3 box blur + edge-clamped np.gradient -> (cos, sin) of atan2
__device__ __forceinline__ void orient(const float* __restrict__ m, int i, int j,
                                       float& cs, float& ss) {
    float patch[5][5];
#pragma unroll
    for (int r = 0; r < 5; r++) {
        int ii = i + r - 2; ii += (ii < 0) ? H : 0; ii -= (ii >= H) ? H : 0;
#pragma unroll
        for (int c = 0; c < 5; c++) {
            int jj = j + c - 2; jj += (jj < 0) ? W : 0; jj -= (jj >= W) ? W : 0;
            patch[r][c] = m[ii*W + jj];
        }
    }
#define BLUR_AT(di, dj) (patch[1+di][1+dj] + patch[1+di][2+dj] + patch[1+di][3+dj] \
                       + patch[2+di][1+dj] + patch[2+di][2+dj] + patch[2+di][3+dj] \
                       + patch[3+di][1+dj] + patch[3+di][2+dj] + patch[3+di][3+dj])
    float byp = BLUR_AT(1, 0), bym = BLUR_AT(-1, 0), bc = BLUR_AT(0, 0);
    float bxp = BLUR_AT(0, 1), bxm = BLUR_AT(0, -1);
#undef BLUR_AT
    float gyv = (i == 0) ? (byp - bc) : (i == H-1) ? (bc - bym) : 0.5f * (byp - bym);
    float gxv = (j == 0) ? (bxp - bc) : (j == W-1) ? (bc - bxm) : 0.5f * (bxp - bxm);
    float r = sqrtf(gxv*gxv + gyv*gyv);
    float cs2, ss2;
    if (r > 0.f) { cs2 = gxv / r; ss2 = gyv / r; }
    else         { cs2 = 1.f;     ss2 = 0.f;     }   // atan2(0,0)=0
    cs = cs2; ss = ss2;
}

// ---------------- K1: fused sparsify + correspondence search + tile binning (R6 structure) ----------------
#define STY 8
#define STX 32
__global__ void __launch_bounds__(STY*STX) k_seed(const float* __restrict__ src,
                                                  const float* __restrict__ dst,
                                                  const int* __restrict__ xx,
                                                  const int* __restrict__ yy, int K) {
    __shared__ int s_pos[48];
    __shared__ int s_cnt;

    int b = blockIdx.z;
    int gy0 = blockIdx.y * STY, gx0 = blockIdx.x * STX;
    int tid = threadIdx.y * STX + threadIdx.x;
    const float* S = src + b*NPIX;
    const float* D = dst + b*NPIX;

    // block (0,0,0): fill the global weight LUT (input-independent, identical every launch).
    // diffuse launches after seed completes -> visibility guaranteed by stream order.
    if (blockIdx.x == 0 && blockIdx.y == 0 && blockIdx.z == 0) {
        for (int h = tid; h < 441; h += STY*STX) {
            int dy = h / 21 - 10, dx = h % 21 - 10;
            g_wk[h] = expf(-sqrtf((float)(dx*dx + dy*dy)) * 0.2f);
        }
    }

    if (tid == 0) s_cnt = 0;
    __syncthreads();

    // phase 1: keep-test (min linear index edge in 5x5 window)
    int i = gy0 + threadIdx.y, j = gx0 + threadIdx.x;
    int p = i*W + j;
    if (S[p] > 0.5f) {
        bool kept = true;
#pragma unroll
        for (int a = -2; a <= 2; a++) {
            int ii = i + a;
            if (ii < 0 || ii >= H) continue;
#pragma unroll
            for (int c = -2; c <= 2; c++) {
                int jj = j + c;
                if (jj < 0 || jj >= W) continue;
                int q = ii*W + jj;
                if (q < p && S[q] > 0.5f) kept = false;
            }
        }
        if (kept) { int idx = atomicAdd(&s_cnt, 1); s_pos[idx] = p; }
    }
    __syncthreads();
    int n = s_cnt;

    // phase 2: warp per kept point, K offsets over lanes
    int warp = tid >> 5, lane = tid & 31;
    for (int pt = warp; pt < n; pt += STY*STX/32) {
        int pp = s_pos[pt];
        int pi = pp / W, pj = pp - (pp / W) * W;
        float cs, ssv;
        orient(S, pi, pj, cs, ssv);   // uniform addresses across warp -> broadcast loads
        float best = 1e9f; int bk = 0x7fffffff;
        for (int k = lane; k < K; k += 32) {
            int ox = xx[k], oy = yy[k];
            int ii = pi + oy, jj = pj + ox;
            if (ii >= 0 && ii < H && jj >= 0 && jj < W) {
                int q = ii*W + jj;
                if (D[q] > 0.5f) {
                    float cd, sd;
                    orient(D, ii, jj, cd, sd);   // rare (~2 hits/point)
                    float ang = 1.0f - (cs*cd + ssv*sd);
                    float sc = 20.0f * sqrtf((float)(ox*ox + oy*oy)) + 10.5f * ang;
                    if (sc < best) { best = sc; bk = k; }
                }
            }
        }
        // warp lexicographic (score, k) min -> global first-index-of-min (argmin semantics)
#pragma unroll
        for (int o = 16; o; o >>= 1) {
            float s2 = __shfl_xor_sync(0xffffffffu, best, o);
            int   k2 = __shfl_xor_sync(0xffffffffu, bk, o);
            if (s2 < best || (s2 == best && k2 < bk)) { best = s2; bk = k2; }
        }
        if (lane == 0 && best < 5e8f) {
            float2 dxy = make_float2((float)xx[bk], (float)yy[bk]);
            int pos = (pi << 16) | pj;
            // bin into every 32x32 output tile whose 52x52 halo contains (pi,pj)
            int tylo = (pi <= 41) ? 0 : ((pi - 41 + 31) >> 5);
            int tyhi = min(TY_N - 1, (pi + 10) >> 5);
            int txlo = (pj <= 41) ? 0 : ((pj - 41 + 31) >> 5);
            int txhi = min(TX_N - 1, (pj + 10) >> 5);
            for (int ty = tylo; ty <= tyhi; ty++)
                for (int tx = txlo; tx <= txhi; tx++) {
                    int tile = (b * TY_N + ty) * TX_N + tx;
                    int idx = atomicAdd(&g_tcnt[tile], 1);
                    if (idx < TCAP) {
                        g_tpos[tile*TCAP + idx] = pos;
                        g_tdxy[tile*TCAP + idx] = dxy;
                    }
                }
        }
    }
}

// ---------------- K2: sparse diffusion; 4 rows per thread, warp-uniform row-band skip ----------------
__global__ void __launch_bounds__(256) k_diffuse(float* __restrict__ out) {
    __shared__ float  s_wk[441];
    __shared__ int    s_pos[TCAP];
    __shared__ float2 s_dxy[TCAP];

    int bb  = blockIdx.z;
    int tid = threadIdx.x;
    int tile = (bb * TY_N + blockIdx.y) * TX_N + blockIdx.x;

    // LUT from global (written by k_seed) -- zero MUFU here
    s_wk[tid] = g_wk[tid < 441 ? tid : 440];
    if (tid + 256 < 441) s_wk[tid + 256] = g_wk[tid + 256];

    int m = min(g_tcnt[tile], TCAP);
    for (int h = tid; h < m; h += 256) {
        s_pos[h] = g_tpos[tile*TCAP + h];
        s_dxy[h] = g_tdxy[tile*TCAP + h];
    }
    if (tid == 0) g_tcnt[tile] = 0;   // self-reset: next launch starts from zero, no memset node
    __syncthreads();

    int w = tid >> 5, lane = tid & 31;
    int ox = blockIdx.x * TS + lane;
    int ybase = blockIdx.y * TS + 4*w;   // this thread owns rows ybase..ybase+3, column ox

    float nx0=0.f,ny0=0.f,dn0=0.f, nx1=0.f,ny1=0.f,dn1=0.f;
    float nx2=0.f,ny2=0.f,dn2=0.f, nx3=0.f,ny3=0.f,dn3=0.f;

    for (int pI = 0; pI < m; pI++) {
        int pos = s_pos[pI];
        int dyb = (pos >> 16) - ybase + HALO;      // warp-uniform
        if ((unsigned)dyb > 23u) continue;         // uniform skip of ~55% of entries
        int ddx = (pos & 0xffff) - ox + HALO;
        if ((unsigned)ddx <= 20u) {
            float2 d = s_dxy[pI];
            int base = dyb * 21 + ddx;
            if ((unsigned) dyb      <= 20u) { float wv = s_wk[base];      nx0 += wv*d.x; ny0 += wv*d.y; dn0 += wv; }
            if ((unsigned)(dyb - 1) <= 20u) { float wv = s_wk[base - 21]; nx1 += wv*d.x; ny1 += wv*d.y; dn1 += wv; }
            if ((unsigned)(dyb - 2) <= 20u) { float wv = s_wk[base - 42]; nx2 += wv*d.x; ny2 += wv*d.y; dn2 += wv; }
            if ((unsigned)(dyb - 3) <= 20u) { float wv = s_wk[base - 63]; nx3 += wv*d.x; ny3 += wv*d.y; dn3 += wv; }
        }
    }

    float* outx = out + (bb*2 + 0)*NPIX;
    float* outy = out + (bb*2 + 1)*NPIX;
    int q = ybase * W + ox;
    float fx = (float)ox;
    float i0 = 1.0f/(dn0+1e-6f); outx[q      ] = fx + 0.6f*nx0*i0; outy[q      ] = (float)(ybase  ) + 0.6f*ny0*i0;
    float i1 = 1.0f/(dn1+1e-6f); outx[q +   W] = fx + 0.6f*nx1*i1; outy[q +   W] = (float)(ybase+1) + 0.6f*ny1*i1;
    float i2 = 1.0f/(dn2+1e-6f); outx[q + 2*W] = fx + 0.6f*nx2*i2; outy[q + 2*W] = (float)(ybase+2) + 0.6f*ny2*i2;
    float i3 = 1.0f/(dn3+1e-6f); outx[q + 3*W] = fx + 0.6f*nx3*i3; outy[q + 3*W] = (float)(ybase+3) + 0.6f*ny3*i3;
}

extern "C" void kernel_launch(void* const* d_in, const int* in_sizes, int n_in,
                              void* d_out, int out_size) {
    const float* src = (const float*)d_in[0];
    const float* dst = (const float*)d_in[1];
    const int*   xx  = (const int*)d_in[2];
    const int*   yy  = (const int*)d_in[3];
    int K = in_sizes[2];
    float* out = (float*)d_out;

    dim3 gs(W/STX, H/STY, BB), ts(STX, STY);
    k_seed<<<gs, ts>>>(src, dst, xx, yy, K);

    dim3 gd(TX_N, TY_N, BB);
    k_diffuse<<<gd, 256>>>(out);
}